// round 13
// baseline (speedup 1.0000x reference)
#include <cuda_runtime.h>
#include <cuda_bf16.h>
#include <cstdint>

// ---------------- problem constants ----------------
#define NB    4096
#define LD_F  1024
#define LD_R  256
#define EPSV  1e-6f
#define NTJ   32                 // 4096/128 tiles per dim
#define NPAIR (NTJ*(NTJ+1)/2)    // 528 tile pairs
#define NOFF  (NPAIR - NTJ)      // 496 off-diagonal pairs

#define KCH         64
#define CHUNK_BYTES 16384        // 128 rows x 64 bf16 (SW128-swizzled)
#define NSTAGE      4
#define STAGE_BYTES (2*CHUNK_BYTES)
#define SMEM_DYN    (NSTAGE*STAGE_BYTES)    // 131072 B

#define KC_R   4                 // 256/64
#define KC_F   16                // 1024/64
// diag tile: 36 chunks ; offdiag tile: 52 chunks

#define GRID_MAIN 152
#define NTHREADS  288            // 1 producer warp + 8 consumer warps

// ---------------- device scratch ----------------
__device__ __align__(16) __nv_bfloat16 g_fb[NB * LD_F];
__device__ __align__(16) __nv_bfloat16 g_nb[NB * LD_F];
__device__ __align__(16) __nv_bfloat16 g_rb[NB * LD_R];
__device__ float g_inv_f[NB];
__device__ float g_inv_n[NB];
__device__ float g_inv_r[NB];
__device__ float g_pos[NB];
__device__ float g_negp[NTJ * NB];
__device__ int   g_work;
__device__ int   g_done;

// ---------------- helpers ----------------
__device__ __forceinline__ uint32_t sptr(const void* p) {
    return (uint32_t)__cvta_generic_to_shared(p);
}
__host__ __device__ __forceinline__ uint32_t sw128(uint32_t o) {
    return o ^ ((o >> 3) & 0x70);
}

#define MBAR_INIT(A, CNT) \
  asm volatile("mbarrier.init.shared.b64 [%0], %1;" :: "r"(A), "r"(CNT) : "memory")
#define MBAR_EXPECT_TX(A, BYTES) \
  asm volatile("mbarrier.arrive.expect_tx.shared.b64 _, [%0], %1;" :: "r"(A), "r"(BYTES) : "memory")
#define MBAR_ARRIVE(A) \
  asm volatile("mbarrier.arrive.shared.b64 _, [%0];" :: "r"(A) : "memory")

__device__ __forceinline__ void mbar_wait(uint32_t addr, uint32_t parity) {
    asm volatile(
        "{\n\t.reg .pred P;\n\t"
        "W_%=:\n\t"
        "mbarrier.try_wait.parity.shared.b64 P, [%0], %1, 0x989680;\n\t"
        "@P bra.uni D_%=;\n\t"
        "bra.uni W_%=;\n\t"
        "D_%=:\n\t}"
        :: "r"(addr), "r"(parity) : "memory");
}

__device__ __forceinline__ void bulk_ld(uint32_t sdst, const void* gsrc,
                                        uint32_t bytes, uint32_t mbar) {
    asm volatile(
        "cp.async.bulk.shared::cluster.global.mbarrier::complete_tx::bytes "
        "[%0], [%1], %2, [%3];"
        :: "r"(sdst), "l"(gsrc), "r"(bytes), "r"(mbar) : "memory");
}

#define LDSM4(R0,R1,R2,R3,ADDR) \
  asm volatile("ldmatrix.sync.aligned.m8n8.x4.shared.b16 {%0,%1,%2,%3}, [%4];" \
    : "=r"(R0),"=r"(R1),"=r"(R2),"=r"(R3) : "r"(ADDR))

#define MMA16816(AC,A0,A1,A2,A3,B0,B1) \
  asm volatile("mma.sync.aligned.m16n8k16.row.col.f32.bf16.bf16.f32 " \
    "{%0,%1,%2,%3},{%4,%5,%6,%7},{%8,%9},{%0,%1,%2,%3};" \
    : "+f"(AC[0]),"+f"(AC[1]),"+f"(AC[2]),"+f"(AC[3]) \
    : "r"(A0),"r"(A1),"r"(A2),"r"(A3),"r"(B0),"r"(B1))

// chunk schedule: g 0=R(ref,ref) 1=S1a(f,noise) 2=S1b(noise,f) 3=S2(f,f)
__device__ __forceinline__ void chunk_map(int c, bool diag, int& g, int& kc) {
    if (c < KC_R)                 { g = 0; kc = c; }
    else if (c < KC_R + KC_F)     { g = 1; kc = c - KC_R; }
    else if (diag)                { g = 3; kc = c - KC_R - KC_F; }
    else if (c < KC_R + 2*KC_F)   { g = 2; kc = c - KC_R - KC_F; }
    else                          { g = 3; kc = c - KC_R - 2*KC_F; }
}

// LPT queue order: 496 offdiag pairs first, 32 diag pairs last
__device__ __forceinline__ void pair_decode(int p, int& bi, int& bj) {
    if (p < NOFF) {
        int k = p; bi = 0;
        while (k >= NTJ - 1 - bi) { k -= NTJ - 1 - bi; bi++; }
        bj = bi + 1 + k;
    } else {
        bi = bj = p - NOFF;
    }
}

// ---------------- fused prep: f / noise (warps 0-3) + ref (warp 4) ----------------
__global__ void prep_kernel(const float* __restrict__ f,
                            const float* __restrict__ nz,
                            const float* __restrict__ ref) {
    int row = blockIdx.x, t = threadIdx.x;
    __shared__ float red[3][4];

    if (t == 0 && row == 0) { g_work = 0; g_done = 0; }

    if (t < 128) {
        int k0 = t * 8;
        const float4* f4 = (const float4*)(f  + (size_t)row * LD_F + k0);
        const float4* n4 = (const float4*)(nz + (size_t)row * LD_F + k0);
        float4 a0 = f4[0], a1 = f4[1];
        float4 b0 = n4[0], b1 = n4[1];

        float sf = a0.x*a0.x+a0.y*a0.y+a0.z*a0.z+a0.w*a0.w
                 + a1.x*a1.x+a1.y*a1.y+a1.z*a1.z+a1.w*a1.w;
        float sn = b0.x*b0.x+b0.y*b0.y+b0.z*b0.z+b0.w*b0.w
                 + b1.x*b1.x+b1.y*b1.y+b1.z*b1.z+b1.w*b1.w;
        float d  = a0.x*b0.x+a0.y*b0.y+a0.z*b0.z+a0.w*b0.w
                 + a1.x*b1.x+a1.y*b1.y+a1.z*b1.z+a1.w*b1.w;

        uint4 pf, pn;
        ((__nv_bfloat162*)&pf)[0] = __floats2bfloat162_rn(a0.x, a0.y);
        ((__nv_bfloat162*)&pf)[1] = __floats2bfloat162_rn(a0.z, a0.w);
        ((__nv_bfloat162*)&pf)[2] = __floats2bfloat162_rn(a1.x, a1.y);
        ((__nv_bfloat162*)&pf)[3] = __floats2bfloat162_rn(a1.z, a1.w);
        ((__nv_bfloat162*)&pn)[0] = __floats2bfloat162_rn(b0.x, b0.y);
        ((__nv_bfloat162*)&pn)[1] = __floats2bfloat162_rn(b0.z, b0.w);
        ((__nv_bfloat162*)&pn)[2] = __floats2bfloat162_rn(b1.x, b1.y);
        ((__nv_bfloat162*)&pn)[3] = __floats2bfloat162_rn(b1.z, b1.w);

        int rb = row >> 7, rloc = row & 127, kc = k0 >> 6, kl = k0 & 63;
        uint32_t off = ((uint32_t)(rloc >> 3) << 10) + ((uint32_t)(rloc & 7) << 7) + (kl << 1);
        uint32_t sw = sw128(off);
        size_t cbase = ((size_t)(rb * KC_F + kc)) << 14;
        *(uint4*)((char*)g_fb + cbase + sw) = pf;
        *(uint4*)((char*)g_nb + cbase + sw) = pn;

#pragma unroll
        for (int o = 16; o; o >>= 1) {
            sf += __shfl_xor_sync(0xffffffffu, sf, o);
            sn += __shfl_xor_sync(0xffffffffu, sn, o);
            d  += __shfl_xor_sync(0xffffffffu, d,  o);
        }
        int lane = t & 31, w = t >> 5;
        if (lane == 0) { red[0][w] = sf; red[1][w] = sn; red[2][w] = d; }
    } else {
        // warp 4: ref row (bf16 + inv norm)
        int lane = t - 128;
        int k0 = lane * 8;
        const float4* r4 = (const float4*)(ref + (size_t)row * LD_R + k0);
        float4 a0 = r4[0], a1 = r4[1];
        float s = a0.x*a0.x+a0.y*a0.y+a0.z*a0.z+a0.w*a0.w
                + a1.x*a1.x+a1.y*a1.y+a1.z*a1.z+a1.w*a1.w;
        uint4 p;
        ((__nv_bfloat162*)&p)[0] = __floats2bfloat162_rn(a0.x, a0.y);
        ((__nv_bfloat162*)&p)[1] = __floats2bfloat162_rn(a0.z, a0.w);
        ((__nv_bfloat162*)&p)[2] = __floats2bfloat162_rn(a1.x, a1.y);
        ((__nv_bfloat162*)&p)[3] = __floats2bfloat162_rn(a1.z, a1.w);

        int rb = row >> 7, rloc = row & 127, kc = k0 >> 6, kl = k0 & 63;
        uint32_t off = ((uint32_t)(rloc >> 3) << 10) + ((uint32_t)(rloc & 7) << 7) + (kl << 1);
        size_t cbase = ((size_t)(rb * KC_R + kc)) << 14;
        *(uint4*)((char*)g_rb + cbase + sw128(off)) = p;

#pragma unroll
        for (int o = 16; o; o >>= 1) s += __shfl_xor_sync(0xffffffffu, s, o);
        if (lane == 0) g_inv_r[row] = 1.f / sqrtf(s);
    }
    __syncthreads();
    if (t == 0) {
        float a = red[0][0]+red[0][1]+red[0][2]+red[0][3];
        float b = red[1][0]+red[1][1]+red[1][2]+red[1][3];
        float c = red[2][0]+red[2][1]+red[2][2]+red[2][3];
        float na = sqrtf(a), nb = sqrtf(b);
        g_inv_f[row] = 1.f / na;
        g_inv_n[row] = 1.f / nb;
        g_pos[row]   = expf(c / fmaxf(na * nb, EPSV));
    }
}

// ---------------- main: persistent CTAs, 8x 64x32 consumer warps + tail finalize ----------------
__global__ void __launch_bounds__(NTHREADS, 1) infonce_main_kernel(float* __restrict__ out) {
    extern __shared__ __align__(128) char dyn[];
    __shared__ __align__(8) uint64_t mb_full[NSTAGE], mb_free[NSTAGE];
    __shared__ float sInvRi[128], sInvRj[128], sInvFi[128], sInvFj[128];
    __shared__ float sInvNi[128], sInvNj[128];
    __shared__ float negp4[4][128];
    __shared__ float cneg2[2][128];
    __shared__ int s_pair;
    __shared__ int s_last;
    __shared__ float red9[9];

    const int tid = threadIdx.x, lane = tid & 31, wid = tid >> 5;
    const uint32_t smem_base = sptr(dyn);

    if (tid == 0) {
#pragma unroll
        for (int s = 0; s < NSTAGE; s++) {
            MBAR_INIT(sptr(&mb_full[s]), 1);
            MBAR_INIT(sptr(&mb_free[s]), 8);
        }
    }

    // consumer geometry (wid 1..8): 64x32 warp tiles
    const int w = wid - 1;
    const int warp_m0 = (w & 1) << 6;      // 0 / 64
    const int warp_n0 = (w >> 1) << 5;     // 0 / 32 / 64 / 96
    const int wc = w >> 1;
    const int mrow_half = w & 1;

    uint32_t aoff[4], axm[4], boff[2], bxm[2];
#pragma unroll
    for (int mi = 0; mi < 4; mi++) {
        int row = warp_m0 + mi * 16 + (lane & 15);
        aoff[mi] = ((uint32_t)(row >> 3) << 10) + ((uint32_t)(row & 7) << 7);
        axm[mi]  = (uint32_t)(row & 7) << 4;
    }
#pragma unroll
    for (int np = 0; np < 2; np++) {
        int row = warp_n0 + np * 16 + ((lane >> 4) << 3) + (lane & 7);
        boff[np] = ((uint32_t)(row >> 3) << 10) + ((uint32_t)(row & 7) << 7);
        bxm[np]  = (uint32_t)(row & 7) << 4;
    }
    const uint32_t akb = (uint32_t)((lane >> 4) << 3) * 2;
    const uint32_t bkb = (uint32_t)(((lane >> 3) & 1) << 3) * 2;

    float acc[4][4][4];
#pragma unroll
    for (int mi = 0; mi < 4; mi++)
#pragma unroll
        for (int ni = 0; ni < 4; ni++)
#pragma unroll
            for (int r = 0; r < 4; r++) acc[mi][ni][r] = 0.f;

    int tc = 0;   // running chunk counter (stage/parity), continues across tiles

    for (;;) {
        if (tid == 0) s_pair = atomicAdd(&g_work, 1);
        __syncthreads();
        const int pair = s_pair;
        if (pair >= NPAIR) break;

        int bi, bj;
        pair_decode(pair, bi, bj);
        const bool diag = (bi == bj);
        const int nch = diag ? (KC_R + 2*KC_F) : (KC_R + 3*KC_F);

        if (tid < 128) {
            sInvRi[tid] = g_inv_r[bi * 128 + tid];
            sInvRj[tid] = g_inv_r[bj * 128 + tid];
            sInvFi[tid] = g_inv_f[bi * 128 + tid];
            sInvFj[tid] = g_inv_f[bj * 128 + tid];
            sInvNi[tid] = g_inv_n[bi * 128 + tid];
            sInvNj[tid] = g_inv_n[bj * 128 + tid];
        }
        __syncthreads();

        if (wid == 0) {
            // ---------------- producer warp ----------------
            const char* gA[4] = {
                (const char*)g_rb + ((size_t)(bi * KC_R) << 14),
                (const char*)g_fb + ((size_t)(bi * KC_F) << 14),
                (const char*)g_nb + ((size_t)(bi * KC_F) << 14),
                (const char*)g_fb + ((size_t)(bi * KC_F) << 14) };
            const char* gB[4] = {
                (const char*)g_rb + ((size_t)(bj * KC_R) << 14),
                (const char*)g_nb + ((size_t)(bj * KC_F) << 14),
                (const char*)g_fb + ((size_t)(bj * KC_F) << 14),
                (const char*)g_fb + ((size_t)(bj * KC_F) << 14) };
#pragma unroll 1
            for (int c = 0; c < nch; c++, tc++) {
                int s = tc & 3;
                if (tc >= NSTAGE) mbar_wait(sptr(&mb_free[s]), ((tc >> 2) - 1) & 1);
                if (lane == 0) {
                    int g, kc; chunk_map(c, diag, g, kc);
                    MBAR_EXPECT_TX(sptr(&mb_full[s]), 2 * CHUNK_BYTES);
                    bulk_ld(smem_base + s * STAGE_BYTES,
                            gA[g] + ((size_t)kc << 14), CHUNK_BYTES, sptr(&mb_full[s]));
                    bulk_ld(smem_base + s * STAGE_BYTES + CHUNK_BYTES,
                            gB[g] + ((size_t)kc << 14), CHUNK_BYTES, sptr(&mb_full[s]));
                }
            }
        } else {
            // ---------------- consumer warps ----------------
            __nv_bfloat162 w2[4][4][2];
            float part[8], cpart[8];
#pragma unroll
            for (int p = 0; p < 8; p++) { part[p] = 0.f; cpart[p] = 0.f; }

#pragma unroll 1
            for (int c = 0; c < nch; c++, tc++) {
                int s = tc & 3;
                mbar_wait(sptr(&mb_full[s]), (tc >> 2) & 1);
                uint32_t cA = smem_base + s * STAGE_BYTES;
                uint32_t cB = cA + CHUNK_BYTES;
#pragma unroll
                for (int kk = 0; kk < KCH; kk += 16) {
                    uint32_t kb = (uint32_t)kk * 2;
                    uint32_t a[4][4];
#pragma unroll
                    for (int mi = 0; mi < 4; mi++)
                        LDSM4(a[mi][0], a[mi][1], a[mi][2], a[mi][3],
                              cA + aoff[mi] + ((kb + akb) ^ axm[mi]));
                    uint32_t b[4][2];
#pragma unroll
                    for (int np = 0; np < 2; np++)
                        LDSM4(b[2*np][0], b[2*np][1], b[2*np+1][0], b[2*np+1][1],
                              cB + boff[np] + ((kb + bkb) ^ bxm[np]));
#pragma unroll
                    for (int mi = 0; mi < 4; mi++)
#pragma unroll
                        for (int ni = 0; ni < 4; ni++)
                            MMA16816(acc[mi][ni], a[mi][0], a[mi][1], a[mi][2], a[mi][3],
                                     b[ni][0], b[ni][1]);
                }
                if (lane == 0) MBAR_ARRIVE(sptr(&mb_free[s]));

                // ---- gemm boundaries ----
                if (c == KC_R - 1) {
                    // R done -> weights (regs)
#pragma unroll
                    for (int mi = 0; mi < 4; mi++)
#pragma unroll
                    for (int ni = 0; ni < 4; ni++)
#pragma unroll
                    for (int rh = 0; rh < 2; rh++) {
                        int row = warp_m0 + mi * 16 + (lane >> 2) + rh * 8;
                        int col = warp_n0 + ni * 8 + (lane & 3) * 2;
                        float invi = sInvRi[row];
                        float w0 = (1.f - acc[mi][ni][rh*2+0] * invi * sInvRj[col])   * 0.5f;
                        float w1 = (1.f - acc[mi][ni][rh*2+1] * invi * sInvRj[col+1]) * 0.5f;
                        w2[mi][ni][rh] = __floats2bfloat162_rn(w0, w1);
                        acc[mi][ni][rh*2+0] = 0.f;
                        acc[mi][ni][rh*2+1] = 0.f;
                    }
                } else if (c == KC_R + KC_F - 1) {
                    // S1a = f_i . noise_j -> row sums
#pragma unroll
                    for (int mi = 0; mi < 4; mi++)
#pragma unroll
                    for (int rh = 0; rh < 2; rh++) {
                        int row = warp_m0 + mi * 16 + (lane >> 2) + rh * 8;
                        float invi = sInvFi[row];
#pragma unroll
                        for (int ni = 0; ni < 4; ni++) {
                            int col = warp_n0 + ni * 8 + (lane & 3) * 2;
                            float2 wf = __bfloat1622float2(w2[mi][ni][rh]);
                            float e0 = wf.x * __expf(acc[mi][ni][rh*2+0] * invi * sInvNj[col]);
                            float e1 = wf.y * __expf(acc[mi][ni][rh*2+1] * invi * sInvNj[col+1]);
                            if (diag && row == col)     e0 = 0.f;
                            if (diag && row == col + 1) e1 = 0.f;
                            part[mi*2+rh] += e0 + e1;
                            acc[mi][ni][rh*2+0] = 0.f;
                            acc[mi][ni][rh*2+1] = 0.f;
                        }
                    }
                } else if (!diag && c == KC_R + 2*KC_F - 1) {
                    // S1b = noise_i . f_j -> col sums
#pragma unroll
                    for (int mi = 0; mi < 4; mi++)
#pragma unroll
                    for (int rh = 0; rh < 2; rh++) {
                        int row = warp_m0 + mi * 16 + (lane >> 2) + rh * 8;
                        float invi = sInvNi[row];
#pragma unroll
                        for (int ni = 0; ni < 4; ni++) {
                            int col = warp_n0 + ni * 8 + (lane & 3) * 2;
                            float2 wf = __bfloat1622float2(w2[mi][ni][rh]);
                            float e0 = wf.x * __expf(acc[mi][ni][rh*2+0] * invi * sInvFj[col]);
                            float e1 = wf.y * __expf(acc[mi][ni][rh*2+1] * invi * sInvFj[col+1]);
                            cpart[ni*2+0] += e0;
                            cpart[ni*2+1] += e1;
                            acc[mi][ni][rh*2+0] = 0.f;
                            acc[mi][ni][rh*2+1] = 0.f;
                        }
                    }
                } else if (c == nch - 1) {
                    // S2 = f_i . f_j -> row sums (+ col sums if offdiag)
#pragma unroll
                    for (int mi = 0; mi < 4; mi++)
#pragma unroll
                    for (int rh = 0; rh < 2; rh++) {
                        int row = warp_m0 + mi * 16 + (lane >> 2) + rh * 8;
                        float invi = sInvFi[row];
#pragma unroll
                        for (int ni = 0; ni < 4; ni++) {
                            int col = warp_n0 + ni * 8 + (lane & 3) * 2;
                            float2 wf = __bfloat1622float2(w2[mi][ni][rh]);
                            float v0 = wf.x * __expf(acc[mi][ni][rh*2+0] * invi * sInvFj[col]);
                            float v1 = wf.y * __expf(acc[mi][ni][rh*2+1] * invi * sInvFj[col+1]);
                            if (diag && row == col)     v0 = 0.f;
                            if (diag && row == col + 1) v1 = 0.f;
                            part[mi*2+rh] += v0 + v1;
                            if (!diag) { cpart[ni*2+0] += v0; cpart[ni*2+1] += v1; }
                            acc[mi][ni][rh*2+0] = 0.f;
                            acc[mi][ni][rh*2+1] = 0.f;
                        }
                    }
                }
            }

            // ---- row reduction ----
#pragma unroll
            for (int p = 0; p < 8; p++) {
                part[p] += __shfl_xor_sync(0xffffffffu, part[p], 1);
                part[p] += __shfl_xor_sync(0xffffffffu, part[p], 2);
            }
            if ((lane & 3) == 0) {
#pragma unroll
                for (int p = 0; p < 8; p++) {
                    int row = warp_m0 + (p >> 1) * 16 + (lane >> 2) + (p & 1) * 8;
                    negp4[wc][row] = part[p];
                }
            }

            // ---- col reduction (offdiag) ----
            if (!diag) {
#pragma unroll
                for (int p = 0; p < 8; p++) {
                    cpart[p] += __shfl_xor_sync(0xffffffffu, cpart[p], 4);
                    cpart[p] += __shfl_xor_sync(0xffffffffu, cpart[p], 8);
                    cpart[p] += __shfl_xor_sync(0xffffffffu, cpart[p], 16);
                }
                if (lane < 4) {
#pragma unroll
                    for (int p = 0; p < 8; p++) {
                        int col = warp_n0 + (p >> 1) * 8 + lane * 2 + (p & 1);
                        cneg2[mrow_half][col] = cpart[p];
                    }
                }
            }
        }

        __syncthreads();
        if (tid < 128) {
            float s = negp4[0][tid] + negp4[1][tid] + negp4[2][tid] + negp4[3][tid];
            g_negp[(size_t)bj * NB + bi * 128 + tid] = s;
            if (!diag)
                g_negp[(size_t)bi * NB + bj * 128 + tid] = cneg2[0][tid] + cneg2[1][tid];
        }
    }

    // ---------------- tail-CTA finalize ----------------
    if (tid == 0) {
        __threadfence();
        s_last = (atomicAdd(&g_done, 1) == GRID_MAIN - 1) ? 1 : 0;
    }
    __syncthreads();
    if (s_last) {
        __threadfence();   // acquire: make all CTAs' g_negp stores visible
        float s = 0.f;
        for (int i = tid; i < NB; i += NTHREADS) {
            float neg = 0.f;
#pragma unroll
            for (int b = 0; b < NTJ; b++) neg += g_negp[(size_t)b * NB + i];
            s += logf(neg + EPSV) - logf(g_pos[i]);
        }
#pragma unroll
        for (int o = 16; o; o >>= 1) s += __shfl_xor_sync(0xffffffffu, s, o);
        if (lane == 0) red9[wid] = s;
        __syncthreads();
        if (tid == 0) {
            float t = 0.f;
#pragma unroll
            for (int i = 0; i < 9; i++) t += red9[i];
            out[0] = t / (float)NB;
        }
    }
}

// ---------------- launch ----------------
extern "C" void kernel_launch(void* const* d_in, const int* in_sizes, int n_in,
                              void* d_out, int out_size) {
    const float* f   = (const float*)d_in[0];
    const float* nz  = (const float*)d_in[1];
    const float* ref = (const float*)d_in[2];
    float* out = (float*)d_out;

    cudaFuncSetAttribute(infonce_main_kernel,
                         cudaFuncAttributeMaxDynamicSharedMemorySize, SMEM_DYN);

    prep_kernel<<<NB, 160>>>(f, nz, ref);
    infonce_main_kernel<<<GRID_MAIN, NTHREADS, SMEM_DYN>>>(out);
}

// round 14
// speedup vs baseline: 1.2744x; 1.2744x over previous
#include <cuda_runtime.h>
#include <cuda_bf16.h>
#include <cstdint>

// ---------------- problem constants ----------------
#define NB    4096
#define LD_F  1024
#define LD_R  256
#define EPSV  1e-6f
#define NTJ   32                 // 4096/128 tiles per dim
#define NPAIR (NTJ*(NTJ+1)/2)    // 528 tile pairs
#define NOFF  (NPAIR - NTJ)      // 496 off-diagonal pairs

#define KCH         64
#define CHUNK_BYTES 16384        // 128 rows x 64 bf16 (SW128-swizzled)
#define NSTAGE      4
#define STAGE_BYTES (2*CHUNK_BYTES)
#define SMEM_DYN    (NSTAGE*STAGE_BYTES)    // 131072 B

#define KC_R   4                 // 256/64
#define KC_F   16                // 1024/64
// diag tile: 36 chunks ; offdiag tile: 52 chunks

#define GRID_MAIN 152
#define NTHREADS  160            // 1 producer warp + 4 consumer warps (measured best)

// ---------------- device scratch ----------------
__device__ __align__(16) __nv_bfloat16 g_fb[NB * LD_F];
__device__ __align__(16) __nv_bfloat16 g_nb[NB * LD_F];
__device__ __align__(16) __nv_bfloat16 g_rb[NB * LD_R];
__device__ float g_inv_f[NB];
__device__ float g_inv_n[NB];
__device__ float g_inv_r[NB];
__device__ float g_pos[NB];
__device__ float g_negp[NTJ * NB];
__device__ float g_loss[NB];
__device__ int   g_work;

// ---------------- helpers ----------------
__device__ __forceinline__ uint32_t sptr(const void* p) {
    return (uint32_t)__cvta_generic_to_shared(p);
}
__host__ __device__ __forceinline__ uint32_t sw128(uint32_t o) {
    return o ^ ((o >> 3) & 0x70);
}

#define MBAR_INIT(A, CNT) \
  asm volatile("mbarrier.init.shared.b64 [%0], %1;" :: "r"(A), "r"(CNT) : "memory")
#define MBAR_EXPECT_TX(A, BYTES) \
  asm volatile("mbarrier.arrive.expect_tx.shared.b64 _, [%0], %1;" :: "r"(A), "r"(BYTES) : "memory")
#define MBAR_ARRIVE(A) \
  asm volatile("mbarrier.arrive.shared.b64 _, [%0];" :: "r"(A) : "memory")

__device__ __forceinline__ void mbar_wait(uint32_t addr, uint32_t parity) {
    asm volatile(
        "{\n\t.reg .pred P;\n\t"
        "W_%=:\n\t"
        "mbarrier.try_wait.parity.shared.b64 P, [%0], %1, 0x989680;\n\t"
        "@P bra.uni D_%=;\n\t"
        "bra.uni W_%=;\n\t"
        "D_%=:\n\t}"
        :: "r"(addr), "r"(parity) : "memory");
}

__device__ __forceinline__ void bulk_ld(uint32_t sdst, const void* gsrc,
                                        uint32_t bytes, uint32_t mbar) {
    asm volatile(
        "cp.async.bulk.shared::cluster.global.mbarrier::complete_tx::bytes "
        "[%0], [%1], %2, [%3];"
        :: "r"(sdst), "l"(gsrc), "r"(bytes), "r"(mbar) : "memory");
}

#define LDSM4(R0,R1,R2,R3,ADDR) \
  asm volatile("ldmatrix.sync.aligned.m8n8.x4.shared.b16 {%0,%1,%2,%3}, [%4];" \
    : "=r"(R0),"=r"(R1),"=r"(R2),"=r"(R3) : "r"(ADDR))

#define MMA16816(AC,A0,A1,A2,A3,B0,B1) \
  asm volatile("mma.sync.aligned.m16n8k16.row.col.f32.bf16.bf16.f32 " \
    "{%0,%1,%2,%3},{%4,%5,%6,%7},{%8,%9},{%0,%1,%2,%3};" \
    : "+f"(AC[0]),"+f"(AC[1]),"+f"(AC[2]),"+f"(AC[3]) \
    : "r"(A0),"r"(A1),"r"(A2),"r"(A3),"r"(B0),"r"(B1))

// chunk schedule: g 0=R(ref,ref) 1=S1a(f,noise) 2=S1b(noise,f) 3=S2(f,f)
__device__ __forceinline__ void chunk_map(int c, bool diag, int& g, int& kc) {
    if (c < KC_R)                 { g = 0; kc = c; }
    else if (c < KC_R + KC_F)     { g = 1; kc = c - KC_R; }
    else if (diag)                { g = 3; kc = c - KC_R - KC_F; }
    else if (c < KC_R + 2*KC_F)   { g = 2; kc = c - KC_R - KC_F; }
    else                          { g = 3; kc = c - KC_R - 2*KC_F; }
}

// LPT queue order: 496 offdiag pairs first, 32 diag pairs last
__device__ __forceinline__ void pair_decode(int p, int& bi, int& bj) {
    if (p < NOFF) {
        int k = p; bi = 0;
        while (k >= NTJ - 1 - bi) { k -= NTJ - 1 - bi; bi++; }
        bj = bi + 1 + k;
    } else {
        bi = bj = p - NOFF;
    }
}

// ---------------- fused prep: f / noise (warps 0-3) + ref (warp 4) ----------------
__global__ void prep_kernel(const float* __restrict__ f,
                            const float* __restrict__ nz,
                            const float* __restrict__ ref) {
    int row = blockIdx.x, t = threadIdx.x;
    __shared__ float red[3][4];

    if (t == 0 && row == 0) g_work = 0;

    if (t < 128) {
        int k0 = t * 8;
        const float4* f4 = (const float4*)(f  + (size_t)row * LD_F + k0);
        const float4* n4 = (const float4*)(nz + (size_t)row * LD_F + k0);
        float4 a0 = f4[0], a1 = f4[1];
        float4 b0 = n4[0], b1 = n4[1];

        float sf = a0.x*a0.x+a0.y*a0.y+a0.z*a0.z+a0.w*a0.w
                 + a1.x*a1.x+a1.y*a1.y+a1.z*a1.z+a1.w*a1.w;
        float sn = b0.x*b0.x+b0.y*b0.y+b0.z*b0.z+b0.w*b0.w
                 + b1.x*b1.x+b1.y*b1.y+b1.z*b1.z+b1.w*b1.w;
        float d  = a0.x*b0.x+a0.y*b0.y+a0.z*b0.z+a0.w*b0.w
                 + a1.x*b1.x+a1.y*b1.y+a1.z*b1.z+a1.w*b1.w;

        uint4 pf, pn;
        ((__nv_bfloat162*)&pf)[0] = __floats2bfloat162_rn(a0.x, a0.y);
        ((__nv_bfloat162*)&pf)[1] = __floats2bfloat162_rn(a0.z, a0.w);
        ((__nv_bfloat162*)&pf)[2] = __floats2bfloat162_rn(a1.x, a1.y);
        ((__nv_bfloat162*)&pf)[3] = __floats2bfloat162_rn(a1.z, a1.w);
        ((__nv_bfloat162*)&pn)[0] = __floats2bfloat162_rn(b0.x, b0.y);
        ((__nv_bfloat162*)&pn)[1] = __floats2bfloat162_rn(b0.z, b0.w);
        ((__nv_bfloat162*)&pn)[2] = __floats2bfloat162_rn(b1.x, b1.y);
        ((__nv_bfloat162*)&pn)[3] = __floats2bfloat162_rn(b1.z, b1.w);

        int rb = row >> 7, rloc = row & 127, kc = k0 >> 6, kl = k0 & 63;
        uint32_t off = ((uint32_t)(rloc >> 3) << 10) + ((uint32_t)(rloc & 7) << 7) + (kl << 1);
        uint32_t sw = sw128(off);
        size_t cbase = ((size_t)(rb * KC_F + kc)) << 14;
        *(uint4*)((char*)g_fb + cbase + sw) = pf;
        *(uint4*)((char*)g_nb + cbase + sw) = pn;

#pragma unroll
        for (int o = 16; o; o >>= 1) {
            sf += __shfl_xor_sync(0xffffffffu, sf, o);
            sn += __shfl_xor_sync(0xffffffffu, sn, o);
            d  += __shfl_xor_sync(0xffffffffu, d,  o);
        }
        int lane = t & 31, w = t >> 5;
        if (lane == 0) { red[0][w] = sf; red[1][w] = sn; red[2][w] = d; }
    } else {
        // warp 4: ref row (bf16 + inv norm)
        int lane = t - 128;
        int k0 = lane * 8;
        const float4* r4 = (const float4*)(ref + (size_t)row * LD_R + k0);
        float4 a0 = r4[0], a1 = r4[1];
        float s = a0.x*a0.x+a0.y*a0.y+a0.z*a0.z+a0.w*a0.w
                + a1.x*a1.x+a1.y*a1.y+a1.z*a1.z+a1.w*a1.w;
        uint4 p;
        ((__nv_bfloat162*)&p)[0] = __floats2bfloat162_rn(a0.x, a0.y);
        ((__nv_bfloat162*)&p)[1] = __floats2bfloat162_rn(a0.z, a0.w);
        ((__nv_bfloat162*)&p)[2] = __floats2bfloat162_rn(a1.x, a1.y);
        ((__nv_bfloat162*)&p)[3] = __floats2bfloat162_rn(a1.z, a1.w);

        int rb = row >> 7, rloc = row & 127, kc = k0 >> 6, kl = k0 & 63;
        uint32_t off = ((uint32_t)(rloc >> 3) << 10) + ((uint32_t)(rloc & 7) << 7) + (kl << 1);
        size_t cbase = ((size_t)(rb * KC_R + kc)) << 14;
        *(uint4*)((char*)g_rb + cbase + sw128(off)) = p;

#pragma unroll
        for (int o = 16; o; o >>= 1) s += __shfl_xor_sync(0xffffffffu, s, o);
        if (lane == 0) g_inv_r[row] = 1.f / sqrtf(s);
    }
    __syncthreads();
    if (t == 0) {
        float a = red[0][0]+red[0][1]+red[0][2]+red[0][3];
        float b = red[1][0]+red[1][1]+red[1][2]+red[1][3];
        float c = red[2][0]+red[2][1]+red[2][2]+red[2][3];
        float na = sqrtf(a), nb = sqrtf(b);
        g_inv_f[row] = 1.f / na;
        g_inv_n[row] = 1.f / nb;
        g_pos[row]   = expf(c / fmaxf(na * nb, EPSV));
    }
}

// ---------------- main: persistent CTAs, 4x 64x64 consumer warps ----------------
__global__ void __launch_bounds__(NTHREADS, 1) infonce_main_kernel() {
    extern __shared__ __align__(128) char dyn[];
    __shared__ __align__(8) uint64_t mb_full[NSTAGE], mb_free[NSTAGE];
    __shared__ float sInvRi[128], sInvRj[128], sInvFi[128], sInvFj[128];
    __shared__ float sInvNi[128], sInvNj[128];
    __shared__ uint32_t sW[128 * 65];         // per-thread weight spill, pitch 65
    __shared__ float negp2r[2][128];
    __shared__ float cneg2[2][128];
    __shared__ int s_pair;

    const int tid = threadIdx.x, lane = tid & 31, wid = tid >> 5;
    const uint32_t smem_base = sptr(dyn);

    if (tid == 0) {
#pragma unroll
        for (int s = 0; s < NSTAGE; s++) {
            MBAR_INIT(sptr(&mb_full[s]), 1);
            MBAR_INIT(sptr(&mb_free[s]), 4);
        }
    }

    // consumer geometry (wid 1..4): 64x64 warp tiles
    const int w = wid - 1;
    const int warp_m0 = (w & 1) << 6;      // 0 / 64
    const int warp_n0 = (w >> 1) << 6;     // 0 / 64
    const int ct = w * 32 + lane;          // consumer thread id 0..127

    uint32_t aoff[4], axm[4], boff[4], bxm[4];
#pragma unroll
    for (int mi = 0; mi < 4; mi++) {
        int row = warp_m0 + mi * 16 + (lane & 15);
        aoff[mi] = ((uint32_t)(row >> 3) << 10) + ((uint32_t)(row & 7) << 7);
        axm[mi]  = (uint32_t)(row & 7) << 4;
    }
#pragma unroll
    for (int np = 0; np < 4; np++) {
        int row = warp_n0 + np * 16 + ((lane >> 4) << 3) + (lane & 7);
        boff[np] = ((uint32_t)(row >> 3) << 10) + ((uint32_t)(row & 7) << 7);
        bxm[np]  = (uint32_t)(row & 7) << 4;
    }
    const uint32_t akb = (uint32_t)((lane >> 4) << 3) * 2;
    const uint32_t bkb = (uint32_t)(((lane >> 3) & 1) << 3) * 2;

    float acc[4][8][4];
#pragma unroll
    for (int mi = 0; mi < 4; mi++)
#pragma unroll
        for (int ni = 0; ni < 8; ni++)
#pragma unroll
            for (int r = 0; r < 4; r++) acc[mi][ni][r] = 0.f;

    int tc = 0;   // running chunk counter (stage/parity), continues across tiles

    for (;;) {
        if (tid == 0) s_pair = atomicAdd(&g_work, 1);
        __syncthreads();
        const int pair = s_pair;
        if (pair >= NPAIR) break;

        int bi, bj;
        pair_decode(pair, bi, bj);
        const bool diag = (bi == bj);
        const int nch = diag ? (KC_R + 2*KC_F) : (KC_R + 3*KC_F);

        if (tid < 128) {
            sInvRi[tid] = g_inv_r[bi * 128 + tid];
            sInvRj[tid] = g_inv_r[bj * 128 + tid];
            sInvFi[tid] = g_inv_f[bi * 128 + tid];
            sInvFj[tid] = g_inv_f[bj * 128 + tid];
            sInvNi[tid] = g_inv_n[bi * 128 + tid];
            sInvNj[tid] = g_inv_n[bj * 128 + tid];
        }
        __syncthreads();

        if (wid == 0) {
            // ---------------- producer warp ----------------
            const char* gA[4] = {
                (const char*)g_rb + ((size_t)(bi * KC_R) << 14),
                (const char*)g_fb + ((size_t)(bi * KC_F) << 14),
                (const char*)g_nb + ((size_t)(bi * KC_F) << 14),
                (const char*)g_fb + ((size_t)(bi * KC_F) << 14) };
            const char* gB[4] = {
                (const char*)g_rb + ((size_t)(bj * KC_R) << 14),
                (const char*)g_nb + ((size_t)(bj * KC_F) << 14),
                (const char*)g_fb + ((size_t)(bj * KC_F) << 14),
                (const char*)g_fb + ((size_t)(bj * KC_F) << 14) };
#pragma unroll 1
            for (int c = 0; c < nch; c++, tc++) {
                int s = tc & 3;
                if (tc >= NSTAGE) mbar_wait(sptr(&mb_free[s]), ((tc >> 2) - 1) & 1);
                if (lane == 0) {
                    int g, kc; chunk_map(c, diag, g, kc);
                    MBAR_EXPECT_TX(sptr(&mb_full[s]), 2 * CHUNK_BYTES);
                    bulk_ld(smem_base + s * STAGE_BYTES,
                            gA[g] + ((size_t)kc << 14), CHUNK_BYTES, sptr(&mb_full[s]));
                    bulk_ld(smem_base + s * STAGE_BYTES + CHUNK_BYTES,
                            gB[g] + ((size_t)kc << 14), CHUNK_BYTES, sptr(&mb_full[s]));
                }
            }
        } else {
            // ---------------- consumer warps ----------------
            float part[8], cpart[16];
#pragma unroll
            for (int p = 0; p < 8; p++) part[p] = 0.f;
#pragma unroll
            for (int p = 0; p < 16; p++) cpart[p] = 0.f;

#pragma unroll 1
            for (int c = 0; c < nch; c++, tc++) {
                int s = tc & 3;
                mbar_wait(sptr(&mb_full[s]), (tc >> 2) & 1);
                uint32_t cA = smem_base + s * STAGE_BYTES;
                uint32_t cB = cA + CHUNK_BYTES;
#pragma unroll
                for (int kk = 0; kk < KCH; kk += 16) {
                    uint32_t kb = (uint32_t)kk * 2;
                    uint32_t a[4][4];
#pragma unroll
                    for (int mi = 0; mi < 4; mi++)
                        LDSM4(a[mi][0], a[mi][1], a[mi][2], a[mi][3],
                              cA + aoff[mi] + ((kb + akb) ^ axm[mi]));
                    uint32_t b[8][2];
#pragma unroll
                    for (int np = 0; np < 4; np++)
                        LDSM4(b[2*np][0], b[2*np][1], b[2*np+1][0], b[2*np+1][1],
                              cB + boff[np] + ((kb + bkb) ^ bxm[np]));
#pragma unroll
                    for (int mi = 0; mi < 4; mi++)
#pragma unroll
                        for (int ni = 0; ni < 8; ni++)
                            MMA16816(acc[mi][ni], a[mi][0], a[mi][1], a[mi][2], a[mi][3],
                                     b[ni][0], b[ni][1]);
                }
                if (lane == 0) MBAR_ARRIVE(sptr(&mb_free[s]));

                // ---- gemm boundaries ----
                if (c == KC_R - 1) {
                    // R done -> weights into sW
#pragma unroll
                    for (int mi = 0; mi < 4; mi++)
#pragma unroll
                    for (int ni = 0; ni < 8; ni++)
#pragma unroll
                    for (int rh = 0; rh < 2; rh++) {
                        int row = warp_m0 + mi * 16 + (lane >> 2) + rh * 8;
                        int col = warp_n0 + ni * 8 + (lane & 3) * 2;
                        float invi = sInvRi[row];
                        float w0 = (1.f - acc[mi][ni][rh*2+0] * invi * sInvRj[col])   * 0.5f;
                        float w1 = (1.f - acc[mi][ni][rh*2+1] * invi * sInvRj[col+1]) * 0.5f;
                        __nv_bfloat162 pw = __floats2bfloat162_rn(w0, w1);
                        sW[ct * 65 + (mi * 8 + ni) * 2 + rh] = *(uint32_t*)&pw;
                        acc[mi][ni][rh*2+0] = 0.f;
                        acc[mi][ni][rh*2+1] = 0.f;
                    }
                } else if (c == KC_R + KC_F - 1) {
                    // S1a = f_i . noise_j -> row sums
#pragma unroll
                    for (int mi = 0; mi < 4; mi++)
#pragma unroll
                    for (int rh = 0; rh < 2; rh++) {
                        int row = warp_m0 + mi * 16 + (lane >> 2) + rh * 8;
                        float invi = sInvFi[row];
#pragma unroll
                        for (int ni = 0; ni < 8; ni++) {
                            int col = warp_n0 + ni * 8 + (lane & 3) * 2;
                            uint32_t wp = sW[ct * 65 + (mi * 8 + ni) * 2 + rh];
                            float2 wf = __bfloat1622float2(*(__nv_bfloat162*)&wp);
                            float e0 = wf.x * __expf(acc[mi][ni][rh*2+0] * invi * sInvNj[col]);
                            float e1 = wf.y * __expf(acc[mi][ni][rh*2+1] * invi * sInvNj[col+1]);
                            if (diag && row == col)     e0 = 0.f;
                            if (diag && row == col + 1) e1 = 0.f;
                            part[mi*2+rh] += e0 + e1;
                            acc[mi][ni][rh*2+0] = 0.f;
                            acc[mi][ni][rh*2+1] = 0.f;
                        }
                    }
                } else if (!diag && c == KC_R + 2*KC_F - 1) {
                    // S1b = noise_i . f_j -> col sums
#pragma unroll
                    for (int mi = 0; mi < 4; mi++)
#pragma unroll
                    for (int rh = 0; rh < 2; rh++) {
                        int row = warp_m0 + mi * 16 + (lane >> 2) + rh * 8;
                        float invi = sInvNi[row];
#pragma unroll
                        for (int ni = 0; ni < 8; ni++) {
                            int col = warp_n0 + ni * 8 + (lane & 3) * 2;
                            uint32_t wp = sW[ct * 65 + (mi * 8 + ni) * 2 + rh];
                            float2 wf = __bfloat1622float2(*(__nv_bfloat162*)&wp);
                            float e0 = wf.x * __expf(acc[mi][ni][rh*2+0] * invi * sInvFj[col]);
                            float e1 = wf.y * __expf(acc[mi][ni][rh*2+1] * invi * sInvFj[col+1]);
                            cpart[ni*2+0] += e0;
                            cpart[ni*2+1] += e1;
                            acc[mi][ni][rh*2+0] = 0.f;
                            acc[mi][ni][rh*2+1] = 0.f;
                        }
                    }
                } else if (c == nch - 1) {
                    // S2 = f_i . f_j -> row sums (+ col sums if offdiag)
#pragma unroll
                    for (int mi = 0; mi < 4; mi++)
#pragma unroll
                    for (int rh = 0; rh < 2; rh++) {
                        int row = warp_m0 + mi * 16 + (lane >> 2) + rh * 8;
                        float invi = sInvFi[row];
#pragma unroll
                        for (int ni = 0; ni < 8; ni++) {
                            int col = warp_n0 + ni * 8 + (lane & 3) * 2;
                            uint32_t wp = sW[ct * 65 + (mi * 8 + ni) * 2 + rh];
                            float2 wf = __bfloat1622float2(*(__nv_bfloat162*)&wp);
                            float v0 = wf.x * __expf(acc[mi][ni][rh*2+0] * invi * sInvFj[col]);
                            float v1 = wf.y * __expf(acc[mi][ni][rh*2+1] * invi * sInvFj[col+1]);
                            if (diag && row == col)     v0 = 0.f;
                            if (diag && row == col + 1) v1 = 0.f;
                            part[mi*2+rh] += v0 + v1;
                            if (!diag) { cpart[ni*2+0] += v0; cpart[ni*2+1] += v1; }
                            acc[mi][ni][rh*2+0] = 0.f;
                            acc[mi][ni][rh*2+1] = 0.f;
                        }
                    }
                }
            }

            // ---- row reduction ----
#pragma unroll
            for (int p = 0; p < 8; p++) {
                part[p] += __shfl_xor_sync(0xffffffffu, part[p], 1);
                part[p] += __shfl_xor_sync(0xffffffffu, part[p], 2);
            }
            if ((lane & 3) == 0) {
#pragma unroll
                for (int p = 0; p < 8; p++) {
                    int row = warp_m0 + (p >> 1) * 16 + (lane >> 2) + (p & 1) * 8;
                    negp2r[w >> 1][row] = part[p];
                }
            }

            // ---- col reduction (offdiag) ----
            if (!diag) {
#pragma unroll
                for (int p = 0; p < 16; p++) {
                    cpart[p] += __shfl_xor_sync(0xffffffffu, cpart[p], 4);
                    cpart[p] += __shfl_xor_sync(0xffffffffu, cpart[p], 8);
                    cpart[p] += __shfl_xor_sync(0xffffffffu, cpart[p], 16);
                }
                if (lane < 4) {
#pragma unroll
                    for (int p = 0; p < 16; p++) {
                        int col = warp_n0 + (p >> 1) * 8 + lane * 2 + (p & 1);
                        cneg2[w & 1][col] = cpart[p];
                    }
                }
            }
        }

        __syncthreads();
        if (tid < 128) {
            g_negp[(size_t)bj * NB + bi * 128 + tid] = negp2r[0][tid] + negp2r[1][tid];
            if (!diag)
                g_negp[(size_t)bi * NB + bj * 128 + tid] = cneg2[0][tid] + cneg2[1][tid];
        }
    }
}

// ---------------- finalize ----------------
__global__ void finalize1_kernel() {
    int gt = blockIdx.x * 128 + threadIdx.x;     // 0..16383
    int i  = gt >> 2;                            // row
    int q  = gt & 3;                             // quarter
    float neg = 0.f;
#pragma unroll
    for (int b = 0; b < 8; b++) neg += g_negp[(size_t)(q * 8 + b) * NB + i];
    neg += __shfl_xor_sync(0xffffffffu, neg, 1);
    neg += __shfl_xor_sync(0xffffffffu, neg, 2);
    if (q == 0) g_loss[i] = logf(neg + EPSV) - logf(g_pos[i]);
}

__global__ void finalize2_kernel(float* __restrict__ out) {
    float s = 0.f;
    for (int i = threadIdx.x; i < NB; i += 256) s += g_loss[i];
#pragma unroll
    for (int o = 16; o; o >>= 1) s += __shfl_xor_sync(0xffffffffu, s, o);
    __shared__ float red[8];
    int lane = threadIdx.x & 31, w = threadIdx.x >> 5;
    if (lane == 0) red[w] = s;
    __syncthreads();
    if (threadIdx.x == 0) {
        float t = 0.f;
        for (int i = 0; i < 8; i++) t += red[i];
        out[0] = t / (float)NB;
    }
}

// ---------------- launch ----------------
extern "C" void kernel_launch(void* const* d_in, const int* in_sizes, int n_in,
                              void* d_out, int out_size) {
    const float* f   = (const float*)d_in[0];
    const float* nz  = (const float*)d_in[1];
    const float* ref = (const float*)d_in[2];
    float* out = (float*)d_out;

    cudaFuncSetAttribute(infonce_main_kernel,
                         cudaFuncAttributeMaxDynamicSharedMemorySize, SMEM_DYN);

    prep_kernel<<<NB, 160>>>(f, nz, ref);
    infonce_main_kernel<<<GRID_MAIN, NTHREADS, SMEM_DYN>>>();
    finalize1_kernel<<<128, 128>>>();
    finalize2_kernel<<<1, 256>>>(out);
}

// round 15
// speedup vs baseline: 1.2898x; 1.0121x over previous
#include <cuda_runtime.h>
#include <cuda_bf16.h>
#include <cstdint>

// ---------------- problem constants ----------------
#define NB    4096
#define LD_F  1024
#define LD_R  256
#define EPSV  1e-6f
#define NTJ   32                 // 4096/128 tiles per dim
#define NPAIR (NTJ*(NTJ+1)/2)    // 528 tile pairs
#define NOFF  (NPAIR - NTJ)      // 496 off-diagonal pairs

#define KCH         64
#define CHUNK_BYTES 16384        // 128 rows x 64 bf16 (SW128-swizzled)
#define NSTAGE      4
#define STAGE_BYTES (2*CHUNK_BYTES)
#define SMEM_DYN    (NSTAGE*STAGE_BYTES)    // 131072 B

#define KC_R   4                 // 256/64
#define KC_F   16                // 1024/64
// diag tile: 36 chunks ; offdiag tile: 52 chunks

#define GRID_MAIN 152
#define NTHREADS  160            // 1 producer warp + 4 consumer warps (measured best)

// ---------------- device scratch ----------------
__device__ __align__(16) __nv_bfloat16 g_fb[NB * LD_F];
__device__ __align__(16) __nv_bfloat16 g_nb[NB * LD_F];
__device__ __align__(16) __nv_bfloat16 g_rb[NB * LD_R];
__device__ float g_inv_f[NB];
__device__ float g_inv_n[NB];
__device__ float g_inv_r[NB];
__device__ float g_pos[NB];
__device__ float g_negp[NTJ * NB];
__device__ float g_part[128];
__device__ int   g_work;

// ---------------- helpers ----------------
__device__ __forceinline__ uint32_t sptr(const void* p) {
    return (uint32_t)__cvta_generic_to_shared(p);
}
__host__ __device__ __forceinline__ uint32_t sw128(uint32_t o) {
    return o ^ ((o >> 3) & 0x70);
}

#define MBAR_INIT(A, CNT) \
  asm volatile("mbarrier.init.shared.b64 [%0], %1;" :: "r"(A), "r"(CNT) : "memory")
#define MBAR_EXPECT_TX(A, BYTES) \
  asm volatile("mbarrier.arrive.expect_tx.shared.b64 _, [%0], %1;" :: "r"(A), "r"(BYTES) : "memory")
#define MBAR_ARRIVE(A) \
  asm volatile("mbarrier.arrive.shared.b64 _, [%0];" :: "r"(A) : "memory")

__device__ __forceinline__ void mbar_wait(uint32_t addr, uint32_t parity) {
    asm volatile(
        "{\n\t.reg .pred P;\n\t"
        "W_%=:\n\t"
        "mbarrier.try_wait.parity.shared.b64 P, [%0], %1, 0x989680;\n\t"
        "@P bra.uni D_%=;\n\t"
        "bra.uni W_%=;\n\t"
        "D_%=:\n\t}"
        :: "r"(addr), "r"(parity) : "memory");
}

__device__ __forceinline__ void bulk_ld(uint32_t sdst, const void* gsrc,
                                        uint32_t bytes, uint32_t mbar) {
    asm volatile(
        "cp.async.bulk.shared::cluster.global.mbarrier::complete_tx::bytes "
        "[%0], [%1], %2, [%3];"
        :: "r"(sdst), "l"(gsrc), "r"(bytes), "r"(mbar) : "memory");
}

#define LDSM4(R0,R1,R2,R3,ADDR) \
  asm volatile("ldmatrix.sync.aligned.m8n8.x4.shared.b16 {%0,%1,%2,%3}, [%4];" \
    : "=r"(R0),"=r"(R1),"=r"(R2),"=r"(R3) : "r"(ADDR))

#define MMA16816(AC,A0,A1,A2,A3,B0,B1) \
  asm volatile("mma.sync.aligned.m16n8k16.row.col.f32.bf16.bf16.f32 " \
    "{%0,%1,%2,%3},{%4,%5,%6,%7},{%8,%9},{%0,%1,%2,%3};" \
    : "+f"(AC[0]),"+f"(AC[1]),"+f"(AC[2]),"+f"(AC[3]) \
    : "r"(A0),"r"(A1),"r"(A2),"r"(A3),"r"(B0),"r"(B1))

// chunk schedule: g 0=R(ref,ref) 1=S1a(f,noise) 2=S1b(noise,f) 3=S2(f,f)
__device__ __forceinline__ void chunk_map(int c, bool diag, int& g, int& kc) {
    if (c < KC_R)                 { g = 0; kc = c; }
    else if (c < KC_R + KC_F)     { g = 1; kc = c - KC_R; }
    else if (diag)                { g = 3; kc = c - KC_R - KC_F; }
    else if (c < KC_R + 2*KC_F)   { g = 2; kc = c - KC_R - KC_F; }
    else                          { g = 3; kc = c - KC_R - 2*KC_F; }
}

// LPT queue order: 496 offdiag pairs first, 32 diag pairs last
__device__ __forceinline__ void pair_decode(int p, int& bi, int& bj) {
    if (p < NOFF) {
        int k = p; bi = 0;
        while (k >= NTJ - 1 - bi) { k -= NTJ - 1 - bi; bi++; }
        bj = bi + 1 + k;
    } else {
        bi = bj = p - NOFF;
    }
}

// ---------------- fused prep: f / noise (warps 0-3) + ref (warp 4) ----------------
__global__ void prep_kernel(const float* __restrict__ f,
                            const float* __restrict__ nz,
                            const float* __restrict__ ref) {
    int row = blockIdx.x, t = threadIdx.x;
    __shared__ float red[3][4];

    if (t == 0 && row == 0) g_work = 0;

    if (t < 128) {
        int k0 = t * 8;
        const float4* f4 = (const float4*)(f  + (size_t)row * LD_F + k0);
        const float4* n4 = (const float4*)(nz + (size_t)row * LD_F + k0);
        float4 a0 = f4[0], a1 = f4[1];
        float4 b0 = n4[0], b1 = n4[1];

        float sf = a0.x*a0.x+a0.y*a0.y+a0.z*a0.z+a0.w*a0.w
                 + a1.x*a1.x+a1.y*a1.y+a1.z*a1.z+a1.w*a1.w;
        float sn = b0.x*b0.x+b0.y*b0.y+b0.z*b0.z+b0.w*b0.w
                 + b1.x*b1.x+b1.y*b1.y+b1.z*b1.z+b1.w*b1.w;
        float d  = a0.x*b0.x+a0.y*b0.y+a0.z*b0.z+a0.w*b0.w
                 + a1.x*b1.x+a1.y*b1.y+a1.z*b1.z+a1.w*b1.w;

        uint4 pf, pn;
        ((__nv_bfloat162*)&pf)[0] = __floats2bfloat162_rn(a0.x, a0.y);
        ((__nv_bfloat162*)&pf)[1] = __floats2bfloat162_rn(a0.z, a0.w);
        ((__nv_bfloat162*)&pf)[2] = __floats2bfloat162_rn(a1.x, a1.y);
        ((__nv_bfloat162*)&pf)[3] = __floats2bfloat162_rn(a1.z, a1.w);
        ((__nv_bfloat162*)&pn)[0] = __floats2bfloat162_rn(b0.x, b0.y);
        ((__nv_bfloat162*)&pn)[1] = __floats2bfloat162_rn(b0.z, b0.w);
        ((__nv_bfloat162*)&pn)[2] = __floats2bfloat162_rn(b1.x, b1.y);
        ((__nv_bfloat162*)&pn)[3] = __floats2bfloat162_rn(b1.z, b1.w);

        int rb = row >> 7, rloc = row & 127, kc = k0 >> 6, kl = k0 & 63;
        uint32_t off = ((uint32_t)(rloc >> 3) << 10) + ((uint32_t)(rloc & 7) << 7) + (kl << 1);
        uint32_t sw = sw128(off);
        size_t cbase = ((size_t)(rb * KC_F + kc)) << 14;
        *(uint4*)((char*)g_fb + cbase + sw) = pf;
        *(uint4*)((char*)g_nb + cbase + sw) = pn;

#pragma unroll
        for (int o = 16; o; o >>= 1) {
            sf += __shfl_xor_sync(0xffffffffu, sf, o);
            sn += __shfl_xor_sync(0xffffffffu, sn, o);
            d  += __shfl_xor_sync(0xffffffffu, d,  o);
        }
        int lane = t & 31, w = t >> 5;
        if (lane == 0) { red[0][w] = sf; red[1][w] = sn; red[2][w] = d; }
    } else {
        // warp 4: ref row (bf16 + inv norm)
        int lane = t - 128;
        int k0 = lane * 8;
        const float4* r4 = (const float4*)(ref + (size_t)row * LD_R + k0);
        float4 a0 = r4[0], a1 = r4[1];
        float s = a0.x*a0.x+a0.y*a0.y+a0.z*a0.z+a0.w*a0.w
                + a1.x*a1.x+a1.y*a1.y+a1.z*a1.z+a1.w*a1.w;
        uint4 p;
        ((__nv_bfloat162*)&p)[0] = __floats2bfloat162_rn(a0.x, a0.y);
        ((__nv_bfloat162*)&p)[1] = __floats2bfloat162_rn(a0.z, a0.w);
        ((__nv_bfloat162*)&p)[2] = __floats2bfloat162_rn(a1.x, a1.y);
        ((__nv_bfloat162*)&p)[3] = __floats2bfloat162_rn(a1.z, a1.w);

        int rb = row >> 7, rloc = row & 127, kc = k0 >> 6, kl = k0 & 63;
        uint32_t off = ((uint32_t)(rloc >> 3) << 10) + ((uint32_t)(rloc & 7) << 7) + (kl << 1);
        size_t cbase = ((size_t)(rb * KC_R + kc)) << 14;
        *(uint4*)((char*)g_rb + cbase + sw128(off)) = p;

#pragma unroll
        for (int o = 16; o; o >>= 1) s += __shfl_xor_sync(0xffffffffu, s, o);
        if (lane == 0) g_inv_r[row] = 1.f / sqrtf(s);
    }
    __syncthreads();
    if (t == 0) {
        float a = red[0][0]+red[0][1]+red[0][2]+red[0][3];
        float b = red[1][0]+red[1][1]+red[1][2]+red[1][3];
        float c = red[2][0]+red[2][1]+red[2][2]+red[2][3];
        float na = sqrtf(a), nb = sqrtf(b);
        g_inv_f[row] = 1.f / na;
        g_inv_n[row] = 1.f / nb;
        g_pos[row]   = expf(c / fmaxf(na * nb, EPSV));
    }
}

// ---------------- main: persistent CTAs, 4x 64x64 consumer warps ----------------
__global__ void __launch_bounds__(NTHREADS, 1) infonce_main_kernel() {
    extern __shared__ __align__(128) char dyn[];
    __shared__ __align__(8) uint64_t mb_full[NSTAGE], mb_free[NSTAGE];
    __shared__ float sInvRi[128], sInvRj[128], sInvFi[128], sInvFj[128];
    __shared__ float sInvNi[128], sInvNj[128];
    __shared__ uint32_t sW[128 * 65];         // per-thread weight spill, pitch 65
    __shared__ float negp2r[2][128];
    __shared__ float cneg2[2][128];
    __shared__ int s_pair;

    const int tid = threadIdx.x, lane = tid & 31, wid = tid >> 5;
    const uint32_t smem_base = sptr(dyn);

    if (tid == 0) {
#pragma unroll
        for (int s = 0; s < NSTAGE; s++) {
            MBAR_INIT(sptr(&mb_full[s]), 1);
            MBAR_INIT(sptr(&mb_free[s]), 4);
        }
    }

    // consumer geometry (wid 1..4): 64x64 warp tiles
    const int w = wid - 1;
    const int warp_m0 = (w & 1) << 6;      // 0 / 64
    const int warp_n0 = (w >> 1) << 6;     // 0 / 64
    const int ct = w * 32 + lane;          // consumer thread id 0..127

    uint32_t aoff[4], axm[4], boff[4], bxm[4];
#pragma unroll
    for (int mi = 0; mi < 4; mi++) {
        int row = warp_m0 + mi * 16 + (lane & 15);
        aoff[mi] = ((uint32_t)(row >> 3) << 10) + ((uint32_t)(row & 7) << 7);
        axm[mi]  = (uint32_t)(row & 7) << 4;
    }
#pragma unroll
    for (int np = 0; np < 4; np++) {
        int row = warp_n0 + np * 16 + ((lane >> 4) << 3) + (lane & 7);
        boff[np] = ((uint32_t)(row >> 3) << 10) + ((uint32_t)(row & 7) << 7);
        bxm[np]  = (uint32_t)(row & 7) << 4;
    }
    const uint32_t akb = (uint32_t)((lane >> 4) << 3) * 2;
    const uint32_t bkb = (uint32_t)(((lane >> 3) & 1) << 3) * 2;

    float acc[4][8][4];
#pragma unroll
    for (int mi = 0; mi < 4; mi++)
#pragma unroll
        for (int ni = 0; ni < 8; ni++)
#pragma unroll
            for (int r = 0; r < 4; r++) acc[mi][ni][r] = 0.f;

    int tc = 0;   // running chunk counter (stage/parity), continues across tiles

    for (;;) {
        if (tid == 0) s_pair = atomicAdd(&g_work, 1);
        __syncthreads();
        const int pair = s_pair;
        if (pair >= NPAIR) break;

        int bi, bj;
        pair_decode(pair, bi, bj);
        const bool diag = (bi == bj);
        const int nch = diag ? (KC_R + 2*KC_F) : (KC_R + 3*KC_F);

        if (tid < 128) {
            sInvRi[tid] = g_inv_r[bi * 128 + tid];
            sInvRj[tid] = g_inv_r[bj * 128 + tid];
            sInvFi[tid] = g_inv_f[bi * 128 + tid];
            sInvFj[tid] = g_inv_f[bj * 128 + tid];
            sInvNi[tid] = g_inv_n[bi * 128 + tid];
            sInvNj[tid] = g_inv_n[bj * 128 + tid];
        }
        __syncthreads();

        if (wid == 0) {
            // ---------------- producer warp ----------------
            const char* gA[4] = {
                (const char*)g_rb + ((size_t)(bi * KC_R) << 14),
                (const char*)g_fb + ((size_t)(bi * KC_F) << 14),
                (const char*)g_nb + ((size_t)(bi * KC_F) << 14),
                (const char*)g_fb + ((size_t)(bi * KC_F) << 14) };
            const char* gB[4] = {
                (const char*)g_rb + ((size_t)(bj * KC_R) << 14),
                (const char*)g_nb + ((size_t)(bj * KC_F) << 14),
                (const char*)g_fb + ((size_t)(bj * KC_F) << 14),
                (const char*)g_fb + ((size_t)(bj * KC_F) << 14) };
#pragma unroll 1
            for (int c = 0; c < nch; c++, tc++) {
                int s = tc & 3;
                if (tc >= NSTAGE) mbar_wait(sptr(&mb_free[s]), ((tc >> 2) - 1) & 1);
                if (lane == 0) {
                    int g, kc; chunk_map(c, diag, g, kc);
                    MBAR_EXPECT_TX(sptr(&mb_full[s]), 2 * CHUNK_BYTES);
                    bulk_ld(smem_base + s * STAGE_BYTES,
                            gA[g] + ((size_t)kc << 14), CHUNK_BYTES, sptr(&mb_full[s]));
                    bulk_ld(smem_base + s * STAGE_BYTES + CHUNK_BYTES,
                            gB[g] + ((size_t)kc << 14), CHUNK_BYTES, sptr(&mb_full[s]));
                }
            }
        } else {
            // ---------------- consumer warps ----------------
            float part[8], cpart[16];
#pragma unroll
            for (int p = 0; p < 8; p++) part[p] = 0.f;
#pragma unroll
            for (int p = 0; p < 16; p++) cpart[p] = 0.f;

#pragma unroll 1
            for (int c = 0; c < nch; c++, tc++) {
                int s = tc & 3;
                mbar_wait(sptr(&mb_full[s]), (tc >> 2) & 1);
                uint32_t cA = smem_base + s * STAGE_BYTES;
                uint32_t cB = cA + CHUNK_BYTES;
#pragma unroll
                for (int kk = 0; kk < KCH; kk += 16) {
                    uint32_t kb = (uint32_t)kk * 2;
                    uint32_t a[4][4];
#pragma unroll
                    for (int mi = 0; mi < 4; mi++)
                        LDSM4(a[mi][0], a[mi][1], a[mi][2], a[mi][3],
                              cA + aoff[mi] + ((kb + akb) ^ axm[mi]));
                    uint32_t b[8][2];
#pragma unroll
                    for (int np = 0; np < 4; np++)
                        LDSM4(b[2*np][0], b[2*np][1], b[2*np+1][0], b[2*np+1][1],
                              cB + boff[np] + ((kb + bkb) ^ bxm[np]));
#pragma unroll
                    for (int mi = 0; mi < 4; mi++)
#pragma unroll
                        for (int ni = 0; ni < 8; ni++)
                            MMA16816(acc[mi][ni], a[mi][0], a[mi][1], a[mi][2], a[mi][3],
                                     b[ni][0], b[ni][1]);
                }
                if (lane == 0) MBAR_ARRIVE(sptr(&mb_free[s]));

                // ---- gemm boundaries ----
                if (c == KC_R - 1) {
                    // R done -> weights into sW
#pragma unroll
                    for (int mi = 0; mi < 4; mi++)
#pragma unroll
                    for (int ni = 0; ni < 8; ni++)
#pragma unroll
                    for (int rh = 0; rh < 2; rh++) {
                        int row = warp_m0 + mi * 16 + (lane >> 2) + rh * 8;
                        int col = warp_n0 + ni * 8 + (lane & 3) * 2;
                        float invi = sInvRi[row];
                        float w0 = (1.f - acc[mi][ni][rh*2+0] * invi * sInvRj[col])   * 0.5f;
                        float w1 = (1.f - acc[mi][ni][rh*2+1] * invi * sInvRj[col+1]) * 0.5f;
                        __nv_bfloat162 pw = __floats2bfloat162_rn(w0, w1);
                        sW[ct * 65 + (mi * 8 + ni) * 2 + rh] = *(uint32_t*)&pw;
                        acc[mi][ni][rh*2+0] = 0.f;
                        acc[mi][ni][rh*2+1] = 0.f;
                    }
                } else if (c == KC_R + KC_F - 1) {
                    // S1a = f_i . noise_j -> row sums
#pragma unroll
                    for (int mi = 0; mi < 4; mi++)
#pragma unroll
                    for (int rh = 0; rh < 2; rh++) {
                        int row = warp_m0 + mi * 16 + (lane >> 2) + rh * 8;
                        float invi = sInvFi[row];
#pragma unroll
                        for (int ni = 0; ni < 8; ni++) {
                            int col = warp_n0 + ni * 8 + (lane & 3) * 2;
                            uint32_t wp = sW[ct * 65 + (mi * 8 + ni) * 2 + rh];
                            float2 wf = __bfloat1622float2(*(__nv_bfloat162*)&wp);
                            float e0 = wf.x * __expf(acc[mi][ni][rh*2+0] * invi * sInvNj[col]);
                            float e1 = wf.y * __expf(acc[mi][ni][rh*2+1] * invi * sInvNj[col+1]);
                            if (diag && row == col)     e0 = 0.f;
                            if (diag && row == col + 1) e1 = 0.f;
                            part[mi*2+rh] += e0 + e1;
                            acc[mi][ni][rh*2+0] = 0.f;
                            acc[mi][ni][rh*2+1] = 0.f;
                        }
                    }
                } else if (!diag && c == KC_R + 2*KC_F - 1) {
                    // S1b = noise_i . f_j -> col sums
#pragma unroll
                    for (int mi = 0; mi < 4; mi++)
#pragma unroll
                    for (int rh = 0; rh < 2; rh++) {
                        int row = warp_m0 + mi * 16 + (lane >> 2) + rh * 8;
                        float invi = sInvNi[row];
#pragma unroll
                        for (int ni = 0; ni < 8; ni++) {
                            int col = warp_n0 + ni * 8 + (lane & 3) * 2;
                            uint32_t wp = sW[ct * 65 + (mi * 8 + ni) * 2 + rh];
                            float2 wf = __bfloat1622float2(*(__nv_bfloat162*)&wp);
                            float e0 = wf.x * __expf(acc[mi][ni][rh*2+0] * invi * sInvFj[col]);
                            float e1 = wf.y * __expf(acc[mi][ni][rh*2+1] * invi * sInvFj[col+1]);
                            cpart[ni*2+0] += e0;
                            cpart[ni*2+1] += e1;
                            acc[mi][ni][rh*2+0] = 0.f;
                            acc[mi][ni][rh*2+1] = 0.f;
                        }
                    }
                } else if (c == nch - 1) {
                    // S2 = f_i . f_j -> row sums (+ col sums if offdiag)
#pragma unroll
                    for (int mi = 0; mi < 4; mi++)
#pragma unroll
                    for (int rh = 0; rh < 2; rh++) {
                        int row = warp_m0 + mi * 16 + (lane >> 2) + rh * 8;
                        float invi = sInvFi[row];
#pragma unroll
                        for (int ni = 0; ni < 8; ni++) {
                            int col = warp_n0 + ni * 8 + (lane & 3) * 2;
                            uint32_t wp = sW[ct * 65 + (mi * 8 + ni) * 2 + rh];
                            float2 wf = __bfloat1622float2(*(__nv_bfloat162*)&wp);
                            float v0 = wf.x * __expf(acc[mi][ni][rh*2+0] * invi * sInvFj[col]);
                            float v1 = wf.y * __expf(acc[mi][ni][rh*2+1] * invi * sInvFj[col+1]);
                            if (diag && row == col)     v0 = 0.f;
                            if (diag && row == col + 1) v1 = 0.f;
                            part[mi*2+rh] += v0 + v1;
                            if (!diag) { cpart[ni*2+0] += v0; cpart[ni*2+1] += v1; }
                            acc[mi][ni][rh*2+0] = 0.f;
                            acc[mi][ni][rh*2+1] = 0.f;
                        }
                    }
                }
            }

            // ---- row reduction ----
#pragma unroll
            for (int p = 0; p < 8; p++) {
                part[p] += __shfl_xor_sync(0xffffffffu, part[p], 1);
                part[p] += __shfl_xor_sync(0xffffffffu, part[p], 2);
            }
            if ((lane & 3) == 0) {
#pragma unroll
                for (int p = 0; p < 8; p++) {
                    int row = warp_m0 + (p >> 1) * 16 + (lane >> 2) + (p & 1) * 8;
                    negp2r[w >> 1][row] = part[p];
                }
            }

            // ---- col reduction (offdiag) ----
            if (!diag) {
#pragma unroll
                for (int p = 0; p < 16; p++) {
                    cpart[p] += __shfl_xor_sync(0xffffffffu, cpart[p], 4);
                    cpart[p] += __shfl_xor_sync(0xffffffffu, cpart[p], 8);
                    cpart[p] += __shfl_xor_sync(0xffffffffu, cpart[p], 16);
                }
                if (lane < 4) {
#pragma unroll
                    for (int p = 0; p < 16; p++) {
                        int col = warp_n0 + (p >> 1) * 8 + lane * 2 + (p & 1);
                        cneg2[w & 1][col] = cpart[p];
                    }
                }
            }
        }

        __syncthreads();
        if (tid < 128) {
            g_negp[(size_t)bj * NB + bi * 128 + tid] = negp2r[0][tid] + negp2r[1][tid];
            if (!diag)
                g_negp[(size_t)bi * NB + bj * 128 + tid] = cneg2[0][tid] + cneg2[1][tid];
        }
    }
}

// ---------------- finalize ----------------
// 128 blocks x 128 threads: 4 threads per row; block reduces its 32 row-losses
// to one deterministic partial.
__global__ void finalize1_kernel() {
    __shared__ float sL[32];
    int t = threadIdx.x;
    int lr = t >> 2;                             // local row 0..31
    int i  = blockIdx.x * 32 + lr;               // global row
    int q  = t & 3;                              // quarter
    float neg = 0.f;
#pragma unroll
    for (int b = 0; b < 8; b++) neg += g_negp[(size_t)(q * 8 + b) * NB + i];
    neg += __shfl_xor_sync(0xffffffffu, neg, 1);
    neg += __shfl_xor_sync(0xffffffffu, neg, 2);
    if (q == 0) sL[lr] = logf(neg + EPSV) - logf(g_pos[i]);
    __syncthreads();
    // deterministic fixed-order tree over 32 values
    if (t < 16) sL[t] += sL[t + 16];
    __syncthreads();
    if (t < 8)  sL[t] += sL[t + 8];
    __syncthreads();
    if (t < 4)  sL[t] += sL[t + 4];
    __syncthreads();
    if (t == 0) g_part[blockIdx.x] = (sL[0] + sL[1]) + (sL[2] + sL[3]);
}

// single warp: deterministic sum of 128 partials
__global__ void finalize2_kernel(float* __restrict__ out) {
    int t = threadIdx.x;                         // 0..31
    float s = (g_part[4*t] + g_part[4*t+1]) + (g_part[4*t+2] + g_part[4*t+3]);
#pragma unroll
    for (int o = 16; o; o >>= 1) s += __shfl_xor_sync(0xffffffffu, s, o);
    if (t == 0) out[0] = s / (float)NB;
}

// ---------------- launch ----------------
extern "C" void kernel_launch(void* const* d_in, const int* in_sizes, int n_in,
                              void* d_out, int out_size) {
    const float* f   = (const float*)d_in[0];
    const float* nz  = (const float*)d_in[1];
    const float* ref = (const float*)d_in[2];
    float* out = (float*)d_out;

    cudaFuncSetAttribute(infonce_main_kernel,
                         cudaFuncAttributeMaxDynamicSharedMemorySize, SMEM_DYN);

    prep_kernel<<<NB, 160>>>(f, nz, ref);
    infonce_main_kernel<<<GRID_MAIN, NTHREADS, SMEM_DYN>>>();
    finalize1_kernel<<<128, 128>>>();
    finalize2_kernel<<<1, 32>>>(out);
}